// round 4
// baseline (speedup 1.0000x reference)
#include <cuda_runtime.h>
#include <cuda_bf16.h>
#include <math.h>

// Problem constants
#define BB 2
#define NN 4096
#define DD 1024
#define HH 16
#define HKV 4
#define DH 64
#define NBUCK 32

// ---------------- scratch (device globals; no allocations allowed) ----------
__device__ float g_zgate[BB*NN*2*DD];     // z | gate         (8192 x 2048)
__device__ float g_zm   [BB*NN*DD];       // silu(zc)*silu(g) (8192 x 1024)
__device__ float g_qgkg [BB*NN*2*DD];     // qg | kg          (8192 x 2048)
__device__ float g_q    [BB*NN*HH*DH];    // q (B,N,H,DH)     (8192 x 1024)
__device__ float g_k    [BB*NN*HKV*DH];   // k (B,N,HKV,DH)
__device__ float g_k2   [BB*NN*HKV*DH];   // pair-transformed k
__device__ float g_v    [BB*NN*HKV*DH];
__device__ float g_base [BB*NN*8];
__device__ int   g_bucket[BB*NN];
__device__ int   g_order [BB*NN];
__device__ float g_Mq[DH*DH];
__device__ float g_Mk[DH*DH];
__device__ float g_o    [BB*NN*HH*DH];    // attention out (B,N,H,DH)

// ---------------- generic fp32 SGEMM: C[M,N] = A[M,K]*B[K,N] ----------------
// BM=128,BN=128,BK=16, 256 threads, 8x8 microtile. M%128==0, N%128==0, K%16==0.
__global__ __launch_bounds__(256) void sgemm128(
    const float* __restrict__ A, int lda,
    const float* __restrict__ B, int ldb,
    float* __restrict__ C, int ldc, int K)
{
    __shared__ float As[16][128];
    __shared__ float Bs[16][128];
    const int tid  = threadIdx.x;
    const int mBase = blockIdx.y * 128;
    const int nBase = blockIdx.x * 128;
    const int trow = (tid / 16) * 8;
    const int tcol = (tid % 16) * 8;
    const int aRow = tid >> 2;          // 0..63
    const int aCol = (tid & 3) << 2;    // 0,4,8,12
    const int bRow = tid >> 5;          // 0..7
    const int bCol = (tid & 31) << 2;   // 0..124

    float acc[8][8];
    #pragma unroll
    for (int i = 0; i < 8; ++i)
        #pragma unroll
        for (int j = 0; j < 8; ++j) acc[i][j] = 0.f;

    const float* Aptr = A + (mBase + aRow) * (size_t)lda + aCol;
    const float* Bptr = B + bRow * (size_t)ldb + nBase + bCol;

    for (int kt = 0; kt < K; kt += 16) {
        float4 a0 = *(const float4*)(Aptr);
        float4 a1 = *(const float4*)(Aptr + 64 * (size_t)lda);
        float4 b0 = *(const float4*)(Bptr);
        float4 b1 = *(const float4*)(Bptr + 8 * (size_t)ldb);
        __syncthreads();
        As[aCol+0][aRow] = a0.x; As[aCol+1][aRow] = a0.y;
        As[aCol+2][aRow] = a0.z; As[aCol+3][aRow] = a0.w;
        As[aCol+0][aRow+64] = a1.x; As[aCol+1][aRow+64] = a1.y;
        As[aCol+2][aRow+64] = a1.z; As[aCol+3][aRow+64] = a1.w;
        *(float4*)&Bs[bRow][bCol]   = b0;
        *(float4*)&Bs[bRow+8][bCol] = b1;
        __syncthreads();
        #pragma unroll
        for (int k = 0; k < 16; ++k) {
            float ar[8], br[8];
            *(float4*)(ar)   = *(const float4*)&As[k][trow];
            *(float4*)(ar+4) = *(const float4*)&As[k][trow+4];
            *(float4*)(br)   = *(const float4*)&Bs[k][tcol];
            *(float4*)(br+4) = *(const float4*)&Bs[k][tcol+4];
            #pragma unroll
            for (int i = 0; i < 8; ++i)
                #pragma unroll
                for (int j = 0; j < 8; ++j)
                    acc[i][j] += ar[i] * br[j];
        }
        Aptr += 16;
        Bptr += 16 * (size_t)ldb;
    }
    #pragma unroll
    for (int i = 0; i < 8; ++i) {
        float* crow = C + (size_t)(mBase + trow + i) * ldc + nBase + tcol;
        ((float4*)crow)[0] = make_float4(acc[i][0], acc[i][1], acc[i][2], acc[i][3]);
        ((float4*)crow)[1] = make_float4(acc[i][4], acc[i][5], acc[i][6], acc[i][7]);
    }
}

// ---------------- depthwise conv (3-tap over N) + SiLU gate -----------------
__device__ __forceinline__ float siluf(float x) { return x / (1.f + expf(-x)); }

__global__ __launch_bounds__(256) void conv_silu_kernel(
    const float* __restrict__ zg, const float* __restrict__ dww,
    const float* __restrict__ dwb, float* __restrict__ zm)
{
    int t = blockIdx.x * 256 + threadIdx.x;      // over B*N*256 float4 groups
    int dq = t & 255;
    int n  = (t >> 8) & 4095;
    int b  = t >> 20;
    int d  = dq * 4;
    const float* zrow = zg + (size_t)(b * 4096 + n) * 2048;
    float4 cur  = *(const float4*)(zrow + d);
    float4 prev = (n > 0)    ? *(const float4*)(zrow - 2048 + d) : make_float4(0,0,0,0);
    float4 next = (n < 4095) ? *(const float4*)(zrow + 2048 + d) : make_float4(0,0,0,0);
    float4 gate = *(const float4*)(zrow + 1024 + d);
    float out[4];
    float pv[4] = {prev.x, prev.y, prev.z, prev.w};
    float cv[4] = {cur.x,  cur.y,  cur.z,  cur.w};
    float nv[4] = {next.x, next.y, next.z, next.w};
    float gv[4] = {gate.x, gate.y, gate.z, gate.w};
    #pragma unroll
    for (int i = 0; i < 4; ++i) {
        int dd = d + i;
        float zc = pv[i]*dww[dd*3+0] + cv[i]*dww[dd*3+1] + nv[i]*dww[dd*3+2] + dwb[dd];
        out[i] = siluf(zc) * siluf(gv[i]);
    }
    *(float4*)(zm + (size_t)(b*4096 + n)*1024 + d) = make_float4(out[0],out[1],out[2],out[3]);
}

// ---------------- base = qg @ base_w  (K=1024, N=8) -------------------------
__global__ __launch_bounds__(256) void base_gemm_kernel(
    const float* __restrict__ A, int lda, const float* __restrict__ Bw,
    float* __restrict__ C)
{
    __shared__ float sB[8192];
    for (int i = threadIdx.x; i < 8192; i += 256) sB[i] = Bw[i];
    __syncthreads();
    int w = threadIdx.x >> 5, lane = threadIdx.x & 31;
    int row = blockIdx.x * 8 + w;
    const float4* Ar = (const float4*)(A + (size_t)row * lda);
    float acc[8] = {0,0,0,0,0,0,0,0};
    #pragma unroll
    for (int it = 0; it < 8; ++it) {
        int q4 = lane + it * 32;
        float4 a = Ar[q4];
        int k = q4 * 4;
        #pragma unroll
        for (int j = 0; j < 8; ++j)
            acc[j] += a.x*sB[k*8+j] + a.y*sB[(k+1)*8+j] + a.z*sB[(k+2)*8+j] + a.w*sB[(k+3)*8+j];
    }
    #pragma unroll
    for (int j = 0; j < 8; ++j)
        #pragma unroll
        for (int s = 16; s; s >>= 1) acc[j] += __shfl_down_sync(0xffffffffu, acc[j], s);
    if (lane == 0) {
        #pragma unroll
        for (int j = 0; j < 8; ++j) C[row*8 + j] = acc[j];
    }
}

// ---------------- LSH hash: sim signs -> XOR salts -> bucket ----------------
__global__ __launch_bounds__(256) void hash_kernel(
    const float* __restrict__ base, const float* __restrict__ rot,
    const int* __restrict__ salts, int* __restrict__ bucket)
{
    __shared__ float srot[256];
    __shared__ int   ss[32];
    if (threadIdx.x < 256) srot[threadIdx.x] = rot[threadIdx.x];
    if (threadIdx.x < 32)  ss[threadIdx.x]   = salts[threadIdx.x];
    __syncthreads();
    int t = blockIdx.x * 256 + threadIdx.x;   // < 8192 tokens
    float bs[8];
    #pragma unroll
    for (int h = 0; h < 8; ++h) bs[h] = base[t*8 + h];
    int code = 0;
    #pragma unroll
    for (int r = 0; r < 4; ++r) {
        int ph = 0;
        #pragma unroll
        for (int kk = 0; kk < 8; ++kk) {
            float s = 0.f;
            #pragma unroll
            for (int h = 0; h < 8; ++h) s += bs[h] * srot[(r*8 + h)*8 + kk];
            if (s >= 0.f) ph ^= ss[r*8 + kk];
        }
        code ^= ph;
    }
    bucket[t] = code & 31;   // code >= 0 (salts have bit31 clear), n_buckets=32
}

// ---------------- stable counting sort (matches stable argsort) -------------
__global__ void sort_kernel(const int* __restrict__ bucket, int* __restrict__ order)
{
    __shared__ int sb[4096];
    int b = blockIdx.x;
    for (int n = threadIdx.x; n < 4096; n += 32) sb[n] = bucket[b*4096 + n];
    __syncwarp();
    int t = threadIdx.x;          // bucket id handled by this lane
    int c = 0;
    for (int n = 0; n < 4096; ++n) c += (sb[n] == t);
    // exclusive prefix over lanes
    int v = c;
    #pragma unroll
    for (int s = 1; s < 32; s <<= 1) {
        int u = __shfl_up_sync(0xffffffffu, v, s);
        if (t >= s) v += u;
    }
    int off = v - c;
    for (int n = 0; n < 4096; ++n)
        if (sb[n] == t) order[b*4096 + (off++)] = n;
}

// ---------------- M = A(64x16) @ B(16x64) -----------------------------------
__global__ void build_M_kernel(const float* __restrict__ Am, const float* __restrict__ Bm,
                               float* __restrict__ Mo)
{
    int t = blockIdx.x * 256 + threadIdx.x;   // 4096
    int d = t >> 6, e = t & 63;
    float acc = 0.f;
    #pragma unroll
    for (int r = 0; r < 16; ++r) acc += Am[d*16 + r] * Bm[r*64 + e];
    Mo[t] = acc;
}

// ---------------- per-vector 64x64 low-rank apply (in place) ----------------
__global__ __launch_bounds__(256) void lowrank_kernel(float* __restrict__ data,
                                                      const float* __restrict__ M)
{
    __shared__ float Ms[4096];
    __shared__ float sIn[4][64];
    for (int i = threadIdx.x; i < 4096; i += 256) Ms[i] = M[i];
    __syncthreads();
    int sub = threadIdx.x >> 6, d = threadIdx.x & 63;
    size_t base = (size_t)blockIdx.x * 64;
    for (int it = 0; it < 16; ++it) {
        size_t v = base + it*4 + sub;
        sIn[sub][d] = data[v*64 + d];
        __syncthreads();
        float acc = 0.f;
        #pragma unroll
        for (int j = 0; j < 64; ++j) acc += sIn[sub][j] * Ms[j*64 + d];
        __syncthreads();
        data[v*64 + d] = acc;
    }
}

// ---------------- k pair transform + channel gate ---------------------------
__global__ __launch_bounds__(256) void pair_gate_kernel(
    const float* __restrict__ kin, float* __restrict__ kout,
    const float* __restrict__ rg)
{
    int t = blockIdx.x * 256 + threadIdx.x;     // B*2048*4*16 = 262144
    int dq = t & 15;
    int h  = (t >> 4) & 3;
    int i  = (t >> 6) & 2047;
    int b  = t >> 17;
    int d  = dq * 4;
    const float* r0 = kin + ((size_t)(b*4096 + 2*i) * 4 + h) * 64 + d;
    const float* r1 = r0 + 256;                 // token 2i+1
    float4 a = *(const float4*)r0;
    float4 c = *(const float4*)r1;
    float g0 = tanhf(1.f + rg[d+0]);
    float g1 = tanhf(1.f + rg[d+1]);
    float g2 = tanhf(1.f + rg[d+2]);
    float g3 = tanhf(1.f + rg[d+3]);
    float4 s = make_float4(0.5f*(a.x+c.x)*g0, 0.5f*(a.y+c.y)*g1,
                           0.5f*(a.z+c.z)*g2, 0.5f*(a.w+c.w)*g3);
    float4 df = make_float4(0.5f*(a.x-c.x)*g0, 0.5f*(a.y-c.y)*g1,
                            0.5f*(a.z-c.z)*g2, 0.5f*(a.w-c.w)*g3);
    *(float4*)(kout + ((size_t)(b*4096 + i)        * 4 + h) * 64 + d) = s;
    *(float4*)(kout + ((size_t)(b*4096 + i + 2048) * 4 + h) * 64 + d) = df;
}

// ---------------- bucketed attention (128x128x64 tiles) ---------------------
__global__ __launch_bounds__(256) void attn_kernel(
    const float* __restrict__ q, const float* __restrict__ k,
    const float* __restrict__ v, const int* __restrict__ order,
    float* __restrict__ o)
{
    extern __shared__ float sm[];
    float* Qs = sm;             // 128*64
    float* Ks = sm + 8192;      // 128*64
    float* Vs = sm + 16384;     // 128*64
    float* S  = sm + 24576;     // 128*128
    int c = blockIdx.x, h = blockIdx.y, b = blockIdx.z;
    int kvh = h >> 2;
    int tid = threadIdx.x;
    int r = tid >> 1, half = tid & 1;
    int tok = order[b*4096 + c*128 + r];
    const float4* qr = (const float4*)(q + (((size_t)(b*4096 + tok))*16 + h)  * 64);
    const float4* kr = (const float4*)(k + (((size_t)(b*4096 + tok))*4 + kvh) * 64);
    const float4* vr = (const float4*)(v + (((size_t)(b*4096 + tok))*4 + kvh) * 64);
    #pragma unroll
    for (int i2 = 0; i2 < 8; ++i2) {
        ((float4*)Qs)[r*16 + half*8 + i2] = qr[half*8 + i2];
        ((float4*)Ks)[r*16 + half*8 + i2] = kr[half*8 + i2];
        ((float4*)Vs)[r*16 + half*8 + i2] = vr[half*8 + i2];
    }
    __syncthreads();
    {   // scores: thread owns row r, half of the j range
        float qreg[64];
        #pragma unroll
        for (int i2 = 0; i2 < 16; ++i2) ((float4*)qreg)[i2] = ((float4*)Qs)[r*16 + i2];
        int j0 = half * 64;
        for (int j = j0; j < j0 + 64; ++j) {
            const float4* kk4 = (const float4*)(Ks + j*64);
            float acc = 0.f;
            #pragma unroll
            for (int d4 = 0; d4 < 16; ++d4) {
                float4 kv = kk4[d4];
                acc += qreg[d4*4+0]*kv.x + qreg[d4*4+1]*kv.y
                     + qreg[d4*4+2]*kv.z + qreg[d4*4+3]*kv.w;
            }
            S[r*128 + j] = acc * 0.125f;
        }
    }
    __syncthreads();
    {   // softmax, warp per row
        int w = tid >> 5, lane = tid & 31;
        for (int row = w; row < 128; row += 8) {
            float4 vv = ((float4*)(S + row*128))[lane];
            float m = fmaxf(fmaxf(vv.x, vv.y), fmaxf(vv.z, vv.w));
            #pragma unroll
            for (int s2 = 16; s2; s2 >>= 1) m = fmaxf(m, __shfl_xor_sync(0xffffffffu, m, s2));
            float e0 = expf(vv.x - m), e1 = expf(vv.y - m);
            float e2 = expf(vv.z - m), e3 = expf(vv.w - m);
            float sum = e0 + e1 + e2 + e3;
            #pragma unroll
            for (int s2 = 16; s2; s2 >>= 1) sum += __shfl_xor_sync(0xffffffffu, sum, s2);
            float inv = 1.f / sum;
            ((float4*)(S + row*128))[lane] = make_float4(e0*inv, e1*inv, e2*inv, e3*inv);
        }
    }
    __syncthreads();
    {   // O = P @ V, scatter rows back to token positions
        float acc[32];
        #pragma unroll
        for (int i2 = 0; i2 < 32; ++i2) acc[i2] = 0.f;
        for (int j = 0; j < 128; ++j) {
            float p = S[r*128 + j];
            const float4* vv4 = (const float4*)(Vs + j*64 + half*32);
            #pragma unroll
            for (int d4 = 0; d4 < 8; ++d4) {
                float4 vv = vv4[d4];
                acc[d4*4+0] += p*vv.x; acc[d4*4+1] += p*vv.y;
                acc[d4*4+2] += p*vv.z; acc[d4*4+3] += p*vv.w;
            }
        }
        float* orow = o + (((size_t)(b*4096 + tok))*16 + h) * 64 + half*32;
        #pragma unroll
        for (int d4 = 0; d4 < 8; ++d4)
            ((float4*)orow)[d4] = make_float4(acc[d4*4], acc[d4*4+1], acc[d4*4+2], acc[d4*4+3]);
    }
}

// ---------------- launcher ---------------------------------------------------
extern "C" void kernel_launch(void* const* d_in, const int* in_sizes, int n_in,
                              void* d_out, int out_size)
{
    const float* x        = (const float*)d_in[0];
    const float* ge_inp_w = (const float*)d_in[1];
    const float* dw_w     = (const float*)d_in[2];
    const float* dw_b     = (const float*)d_in[3];
    const float* ge_out_w = (const float*)d_in[4];
    const float* q_w      = (const float*)d_in[5];
    const float* k_w      = (const float*)d_in[6];
    const float* v_w      = (const float*)d_in[7];
    const float* Aq       = (const float*)d_in[8];
    const float* Bq       = (const float*)d_in[9];
    const float* Ak       = (const float*)d_in[10];
    const float* Bk       = (const float*)d_in[11];
    const float* rand_gate= (const float*)d_in[12];
    const float* base_w   = (const float*)d_in[13];
    const float* rot      = (const float*)d_in[14];
    // d_in[15] = u (unused by reference)
    const float* o_w      = (const float*)d_in[16];
    const int*   salts    = (const int*)d_in[17];
    float* out = (float*)d_out;

    float *zgate, *zm, *qgkg, *qb, *kb, *k2b, *vb, *baseb, *Mq, *Mk, *ob;
    int *bucket, *order;
    cudaGetSymbolAddress((void**)&zgate, g_zgate);
    cudaGetSymbolAddress((void**)&zm,    g_zm);
    cudaGetSymbolAddress((void**)&qgkg,  g_qgkg);
    cudaGetSymbolAddress((void**)&qb,    g_q);
    cudaGetSymbolAddress((void**)&kb,    g_k);
    cudaGetSymbolAddress((void**)&k2b,   g_k2);
    cudaGetSymbolAddress((void**)&vb,    g_v);
    cudaGetSymbolAddress((void**)&baseb, g_base);
    cudaGetSymbolAddress((void**)&bucket,g_bucket);
    cudaGetSymbolAddress((void**)&order, g_order);
    cudaGetSymbolAddress((void**)&Mq,    g_Mq);
    cudaGetSymbolAddress((void**)&Mk,    g_Mk);
    cudaGetSymbolAddress((void**)&ob,    g_o);

    const int M = BB * NN;   // 8192

    // G1: x @ ge_inp_w -> z|gate
    sgemm128<<<dim3(2048/128, M/128), 256>>>(x, 1024, ge_inp_w, 2048, zgate, 2048, 1024);
    // conv + silu
    conv_silu_kernel<<<(BB*NN*256)/256, 256>>>(zgate, dw_w, dw_b, zm);
    // G2: zm @ ge_out_w -> qg|kg
    sgemm128<<<dim3(2048/128, M/128), 256>>>(zm, 1024, ge_out_w, 2048, qgkg, 2048, 1024);
    // G3: qg @ q_w -> q
    sgemm128<<<dim3(1024/128, M/128), 256>>>(qgkg, 2048, q_w, 1024, qb, 1024, 1024);
    // G4: kg @ k_w -> k
    sgemm128<<<dim3(256/128, M/128), 256>>>(qgkg + 1024, 2048, k_w, 256, kb, 256, 1024);
    // G5: x @ v_w -> v
    sgemm128<<<dim3(256/128, M/128), 256>>>(x, 1024, v_w, 256, vb, 256, 1024);
    // base = qg @ base_w
    base_gemm_kernel<<<M/8, 256>>>(qgkg, 2048, base_w, baseb);
    // hash + stable sort
    hash_kernel<<<M/256, 256>>>(baseb, rot, salts, bucket);
    sort_kernel<<<BB, 32>>>(bucket, order);
    // low-rank maps
    build_M_kernel<<<16, 256>>>(Aq, Bq, Mq);
    build_M_kernel<<<16, 256>>>(Ak, Bk, Mk);
    lowrank_kernel<<<(M*HH)/64, 256>>>(qb, Mq);
    lowrank_kernel<<<(M*HKV)/64, 256>>>(kb, Mk);
    // k pair transform + gate
    pair_gate_kernel<<<(BB*2048*4*16)/256, 256>>>(kb, k2b, rand_gate);
    // attention
    static const int ATTN_SMEM = (3*128*64 + 128*128) * 4;   // 163840
    cudaFuncSetAttribute(attn_kernel, cudaFuncAttributeMaxDynamicSharedMemorySize, ATTN_SMEM);
    attn_kernel<<<dim3(32, HH, BB), 256, ATTN_SMEM>>>(qb, k2b, vb, order, ob);
    // output projection
    sgemm128<<<dim3(1024/128, M/128), 256>>>(ob, 1024, o_w, 1024, out, 1024, 1024);
}